// round 11
// baseline (speedup 1.0000x reference)
#include <cuda_runtime.h>
#include <cstdint>

// Problem constants (fixed by setup_inputs)
#define B_   16
#define T_   8192
#define C_   256
#define STRIDE_ 64
#define NCHUNK_ 126          // (T_ - W0_) / STRIDE_
#define W0_  128
#define W1_  64
#define W2_  16

// Output offsets (float elements), leaf order: K0,V0,K1,V1,K2,V2,recon
#define K0_OFF  0
#define V0_OFF  (B_*W0_*C_)                    // 524288
#define K1_OFF  (V0_OFF + B_*W0_*C_)           // 1048576
#define V1_OFF  (K1_OFF + B_*W1_*C_)           // 1310720
#define K2_OFF  (V1_OFF + B_*W1_*C_)           // 1572864
#define V2_OFF  (K2_OFF + B_*W2_*C_)           // 1638400
#define RECON_OFF (V2_OFF + B_*W2_*C_)         // 1703936

#define NBLK1 (B_*NCHUNK_)   // 2016 pooling blocks
#define NCOPYBLK 128         // 128 blocks * 256 thr * 4 float4 = 131072 = B_*W0_*C_/4
#define NBLK2 (B_*32)        // 512

__device__ float g_part1[NBLK1];
__device__ float g_part2[NBLK2];
__device__ unsigned int g_done2 = 0;   // level-2 completion counter (self-resetting)

// ---------------------------------------------------------------------------
// Kernel 1: K0/V0 copy (blocks [0, NCOPYBLK)) + level-1 pooling (blocks
// [NCOPYBLK, NCOPYBLK+NBLK1)). 256 threads.
// Dynamic smem: Ks[64*256] + q0s[256] + w[64] + red[32] = 66,944 B -> 3 CTA/SM
// ---------------------------------------------------------------------------
__global__ __launch_bounds__(256) void level1_kernel(
        const float* __restrict__ K, const float* __restrict__ V,
        const float* __restrict__ q0, float* __restrict__ out) {
    const int tid  = threadIdx.x;

    // ---- Copy blocks first: K0 = K[:, T-128:], V0 = V[:, T-128:] --------
    // Each block copies 1024 contiguous float4 (4 per thread) of both K and V.
    // per_b = 8192 float4; 1024 | 8192, so a block never straddles batches.
    // 8 independent LDG.128 in flight per thread (deep MLP for DRAM latency).
    if (blockIdx.x < NCOPYBLK) {
        const float4* K4 = reinterpret_cast<const float4*>(K);
        const float4* V4 = reinterpret_cast<const float4*>(V);
        float4* out4 = reinterpret_cast<float4*>(out);
        const int C4 = C_ / 4;                 // 64
        const int per_b = W0_ * C4;            // 8192 float4 per batch tile
        const int blk_base = blockIdx.x * 1024;
        const int b = blk_base / per_b;
        const size_t src_base =
            ((size_t)b * T_ + (T_ - W0_)) * C4 + (blk_base % per_b);
        float4 kv[4], vv[4];
        #pragma unroll
        for (int j = 0; j < 4; j++) kv[j] = __ldcs(&K4[src_base + j * 256 + tid]);
        #pragma unroll
        for (int j = 0; j < 4; j++) vv[j] = __ldcs(&V4[src_base + j * 256 + tid]);
        #pragma unroll
        for (int j = 0; j < 4; j++) {
            int i = blk_base + j * 256 + tid;
            __stcs(&out4[K0_OFF / 4 + i], kv[j]);
            __stcs(&out4[V0_OFF / 4 + i], vv[j]);
        }
        return;
    }

    // ---- Pooling blocks -------------------------------------------------
    extern __shared__ float sm[];
    float* Ks  = sm;                 // 64*256
    float* q0s = Ks + 64 * C_;       // 256
    float* wsh = q0s + C_;           // 64
    float* red = wsh + 64;           // 32

    const int lane = tid & 31;
    const int wid  = tid >> 5;

    const int pb = blockIdx.x - NCOPYBLK;     // 0 .. NBLK1-1
    const int b = pb / NCHUNK_;
    const int n = pb % NCHUNK_;
    const size_t base = ((size_t)b * T_ + (size_t)n * STRIDE_) * C_;

    // Stage K chunk into smem (float4, evict-first: single DRAM touch)
    {
        const float4* Kg  = reinterpret_cast<const float4*>(K + base);
        float4*       Ks4 = reinterpret_cast<float4*>(Ks);
        #pragma unroll
        for (int i = 0; i < 16; i++)
            Ks4[i * 256 + tid] = __ldcs(&Kg[i * 256 + tid]);
        q0s[tid] = q0[tid];
    }
    __syncthreads();

    // Logits: warp wid handles rows s = wid*8 .. wid*8+7 (conflict-free LDS)
    {
        float qv[8];
        #pragma unroll
        for (int i = 0; i < 8; i++) qv[i] = q0s[lane + 32 * i];
        #pragma unroll
        for (int r = 0; r < 8; r++) {
            int s = wid * 8 + r;
            const float* row = Ks + s * C_;
            float acc = 0.f;
            #pragma unroll
            for (int i = 0; i < 8; i++) acc = fmaf(row[lane + 32 * i], qv[i], acc);
            #pragma unroll
            for (int off = 16; off; off >>= 1)
                acc += __shfl_xor_sync(0xffffffffu, acc, off);
            if (lane == 0) wsh[s] = acc;
        }
    }
    __syncthreads();

    // Softmax over 64 logits (warp 0), max-subtracted
    if (wid == 0) {
        float l0 = wsh[lane], l1 = wsh[lane + 32];
        float m = fmaxf(l0, l1);
        #pragma unroll
        for (int off = 16; off; off >>= 1)
            m = fmaxf(m, __shfl_xor_sync(0xffffffffu, m, off));
        float e0 = __expf(l0 - m), e1 = __expf(l1 - m);
        float ssum = e0 + e1;
        #pragma unroll
        for (int off = 16; off; off >>= 1)
            ssum += __shfl_xor_sync(0xffffffffu, ssum, off);
        float inv = 1.f / ssum;
        wsh[lane] = e0 * inv;
        wsh[lane + 32] = e1 * inv;
    }
    __syncthreads();

    // Per-column (thread = column c) merged pass:
    //   sk, sum(x), sum(x^2) from smem K; sv streamed from global V.
    // Merging lets ptxas batch the long-latency V loads behind smem FMAs.
    const int c = tid;
    const float* Vg = V + base;
    float sk = 0.f, sx = 0.f, sxx = 0.f, sv = 0.f;
    #pragma unroll 8
    for (int s = 0; s < 64; s++) {
        float w = wsh[s];                    // broadcast LDS (free)
        float v = __ldcs(&Vg[s * C_ + c]);   // single-use stream, evict-first
        float x = Ks[s * C_ + c];
        sk  = fmaf(w, x, sk);
        sx += x;
        sxx = fmaf(x, x, sxx);
        sv  = fmaf(w, v, sv);
    }
    // sum_s (x - sk)^2 = sxx - 2*sk*sx + 64*sk^2  (no cancellation risk @N(0,1))
    float rp = sxx - 2.f * sk * sx + 64.f * sk * sk;

    // Outputs: only last W1_ chunks feed K1/V1
    if (n >= NCHUNK_ - W1_) {
        int j = n - (NCHUNK_ - W1_);
        size_t o = ((size_t)b * W1_ + j) * C_ + c;
        out[K1_OFF + o] = sk;
        out[V1_OFF + o] = sv;
    }

    // Block-reduce rp -> g_part1 (deterministic: fixed tree, fixed mapping)
    #pragma unroll
    for (int off = 16; off; off >>= 1)
        rp += __shfl_xor_sync(0xffffffffu, rp, off);
    if (lane == 0) red[wid] = rp;
    __syncthreads();
    if (wid == 0) {
        float v = (lane < 8) ? red[lane] : 0.f;
        #pragma unroll
        for (int off = 4; off; off >>= 1)
            v += __shfl_xor_sync(0xffffffffu, v, off);
        if (lane == 0)
            // rl[n] = sum/(B*stride*C); recon1 = sum_n rl[n] / NCHUNK
            g_part1[pb] = v * (1.0f / ((float)(B_ * STRIDE_ * C_) * (float)NCHUNK_));
    }
}

// ---------------------------------------------------------------------------
// Kernel 2: level-2 pooling over K1/V1 pairs. One block per (b, pair). 256 thr.
// The LAST block to finish also performs the recon reduction. Election order
// only picks WHICH block sums; index order + thread mapping are fixed, so the
// result is bit-identical on every graph replay.
// ---------------------------------------------------------------------------
__global__ __launch_bounds__(256) void level2_kernel(
        const float* __restrict__ out_in, const float* __restrict__ q1,
        float* __restrict__ out) {
    __shared__ float red0[8], red1[8], lsh[2];
    __shared__ unsigned int s_last;

    const int tid  = threadIdx.x;
    const int lane = tid & 31;
    const int wid  = tid >> 5;
    const int b = blockIdx.x >> 5;
    const int p = blockIdx.x & 31;
    const int c = tid;

    const float* K1 = out_in + K1_OFF;
    const float* V1 = out_in + V1_OFF;
    size_t r0 = ((size_t)b * W1_ + 2 * p) * C_ + c;
    float k0 = K1[r0], k1 = K1[r0 + C_];
    float v0 = V1[r0], v1 = V1[r0 + C_];
    float qc = q1[c];

    float d0 = k0 * qc, d1 = k1 * qc;
    #pragma unroll
    for (int off = 16; off; off >>= 1) {
        d0 += __shfl_xor_sync(0xffffffffu, d0, off);
        d1 += __shfl_xor_sync(0xffffffffu, d1, off);
    }
    if (lane == 0) { red0[wid] = d0; red1[wid] = d1; }
    __syncthreads();
    if (tid == 0) {
        float l0 = 0.f, l1 = 0.f;
        #pragma unroll
        for (int i = 0; i < 8; i++) { l0 += red0[i]; l1 += red1[i]; }
        lsh[0] = l0; lsh[1] = l1;
    }
    __syncthreads();
    float l0 = lsh[0], l1 = lsh[1];
    float m = fmaxf(l0, l1);
    float e0 = __expf(l0 - m), e1 = __expf(l1 - m);
    float inv = 1.f / (e0 + e1);
    float w0 = e0 * inv, w1 = e1 * inv;

    float sk = w0 * k0 + w1 * k1;
    float sv = w0 * v0 + w1 * v1;

    if (p >= 32 - W2_) {
        int j = p - (32 - W2_);
        size_t o = ((size_t)b * W2_ + j) * C_ + c;
        out[K2_OFF + o] = sk;
        out[V2_OFF + o] = sv;
    }

    float dd0 = k0 - sk, dd1 = k1 - sk;
    float rp = dd0 * dd0 + dd1 * dd1;
    #pragma unroll
    for (int off = 16; off; off >>= 1)
        rp += __shfl_xor_sync(0xffffffffu, rp, off);
    if (lane == 0) red0[wid] = rp;
    __syncthreads();
    if (tid == 0) {
        float v = 0.f;
        #pragma unroll
        for (int i = 0; i < 8; i++) v += red0[i];
        // rl2[p] = sum/(B*2*C); recon2 = 0.5 * sum_p rl2[p]
        g_part2[blockIdx.x] = 0.5f * v * (1.0f / (float)(B_ * 2 * C_));
    }

    // ---- Last-block-done recon reduction --------------------------------
    if (tid == 0) {
        __threadfence();                       // make g_part2 write visible
        unsigned int t = atomicAdd(&g_done2, 1u);
        s_last = (t == NBLK2 - 1) ? 1u : 0u;
    }
    __syncthreads();
    if (s_last) {
        __threadfence();                       // acquire all blocks' partials
        float a = 0.f;
        for (int i = tid; i < NBLK1; i += 256) a += g_part1[i];
        for (int i = tid; i < NBLK2; i += 256) a += g_part2[i];
        #pragma unroll
        for (int off = 16; off; off >>= 1)
            a += __shfl_xor_sync(0xffffffffu, a, off);
        if (lane == 0) red0[wid] = a;
        __syncthreads();
        if (tid == 0) {
            float v = 0.f;
            #pragma unroll
            for (int i = 0; i < 8; i++) v += red0[i];
            out[RECON_OFF] = v;
            g_done2 = 0;                       // reset for next graph replay
        }
    }
}

// ---------------------------------------------------------------------------
extern "C" void kernel_launch(void* const* d_in, const int* in_sizes, int n_in,
                              void* d_out, int out_size) {
    const float* K  = (const float*)d_in[0];
    const float* V  = (const float*)d_in[1];
    const float* q0 = (const float*)d_in[2];
    const float* q1 = (const float*)d_in[3];
    float* out = (float*)d_out;

    // smem for level1: (64*256 + 256 + 64 + 32) floats = 66,944 bytes
    const int smem1 = (64 * C_ + C_ + 64 + 32) * sizeof(float);
    cudaFuncSetAttribute(level1_kernel,
                         cudaFuncAttributeMaxDynamicSharedMemorySize, smem1);

    // K0/V0 copy (front blocks) + level-1 pooling in one grid
    level1_kernel<<<NCOPYBLK + NBLK1, 256, smem1>>>(K, V, q0, out);
    // Level 2 (depends on K1/V1) + fused deterministic recon reduction
    level2_kernel<<<NBLK2, 256>>>(out, q1, out);
}